// round 8
// baseline (speedup 1.0000x reference)
#include <cuda_runtime.h>
#include <cstdint>

#define NB 4
#define A_TOTAL 159882
#define K_TOTAL 4507
#define POST_NMS 1000
#define NTASK (NB * 5)
#define HB 4096             // 12-bit histogram bins
#define HSHIFT 20
#define CCAP 4096
#define NSLICE 44           // work-balanced slices per batch image

__constant__ int c_lvl_n[5]    = {120000, 30000, 7500, 1875, 507};
__constant__ int c_lvl_base[5] = {0, 120000, 150000, 157500, 159375};
__constant__ int c_lvl_k[5]    = {1000, 1000, 1000, 1000, 507};
__constant__ int c_nblk[5]     = {32, 8, 2, 1, 1};

// supmask triangular tiles: (jc: j-block of 256, ic: i-block of 32),
// tile present iff ic <= 8*jc+7 -> 80 tiles
__constant__ unsigned char c_tjc[80] = {
    0,0,0,0,0,0,0,0,
    1,1,1,1,1,1,1,1,1,1,1,1,1,1,1,1,
    2,2,2,2,2,2,2,2,2,2,2,2,2,2,2,2,2,2,2,2,2,2,2,2,
    3,3,3,3,3,3,3,3,3,3,3,3,3,3,3,3,3,3,3,3,3,3,3,3,3,3,3,3,3,3,3,3};
__constant__ unsigned char c_tic[80] = {
    0,1,2,3,4,5,6,7,
    0,1,2,3,4,5,6,7,8,9,10,11,12,13,14,15,
    0,1,2,3,4,5,6,7,8,9,10,11,12,13,14,15,16,17,18,19,20,21,22,23,
    0,1,2,3,4,5,6,7,8,9,10,11,12,13,14,15,16,17,18,19,20,21,22,23,
    24,25,26,27,28,29,30,31};

// static scratch (no allocation; zero-initialized at load; every kernel that
// dirties a buffer restores it before exit -> replay-invariant)
__device__ unsigned           d_hist[NTASK * HB];
__device__ int                d_taskbar[NTASK];
__device__ int                d_bar[NB];
__device__ float              d_boxes[NB * K_TOTAL * 4];
__device__ float              d_score[NB * K_TOTAL];
__device__ float4             d_sbx[NTASK * 1024];
__device__ float              d_sar[NTASK * 1024];
__device__ unsigned long long d_skey[NTASK * 1024];
__device__ unsigned           d_valmask[NTASK * 32];
__device__ unsigned           d_sup[NTASK * 1024 * 32];
__device__ unsigned long long d_lvl_keys[NTASK * 1024];
__device__ int                d_lvl_cnt[NTASK];

__device__ __forceinline__ unsigned xf32(float f) {
    unsigned u = __float_as_uint(f);
    return (u & 0x80000000u) ? ~u : (u | 0x80000000u);
}

// slice table: index -> (lvl, s0). counts {32,8,2,1,1}, chunk 3750.
__device__ __forceinline__ void slice_of(int s, int& lvl, int& s0) {
    if (s < 32)      { lvl = 0; s0 = s * 3750; }
    else if (s < 40) { lvl = 1; s0 = (s - 32) * 3750; }
    else if (s < 42) { lvl = 2; s0 = (s - 40) * 3750; }
    else if (s == 42){ lvl = 3; s0 = 0; }
    else             { lvl = 4; s0 = 0; }
}

// ---------------------------------------------------------------------------
// Hybrid bitonic sort: 1024 u64 keys descending, one per thread.
// ---------------------------------------------------------------------------
__device__ __forceinline__ unsigned long long
bsort1024(unsigned long long v, unsigned long long* sbuf, int tid) {
    #pragma unroll
    for (unsigned sz = 2; sz <= 32; sz <<= 1) {
        #pragma unroll
        for (unsigned j = sz >> 1; j; j >>= 1) {
            unsigned long long pv = __shfl_xor_sync(0xffffffffu, v, j);
            bool takeMax = (((tid & sz) == 0) == ((tid & j) == 0));
            v = takeMax ? (v > pv ? v : pv) : (v < pv ? v : pv);
        }
    }
    #pragma unroll
    for (unsigned sz = 64; sz <= 1024; sz <<= 1) {
        #pragma unroll 1
        for (unsigned j = sz >> 1; j >= 32; j >>= 1) {
            sbuf[tid] = v;
            __syncthreads();
            unsigned long long pv = sbuf[tid ^ j];
            bool takeMax = (((tid & sz) == 0) == ((tid & j) == 0));
            v = takeMax ? (v > pv ? v : pv) : (v < pv ? v : pv);
            __syncthreads();
        }
        #pragma unroll
        for (unsigned j = 16; j; j >>= 1) {
            unsigned long long pv = __shfl_xor_sync(0xffffffffu, v, j);
            bool takeMax = (((tid & sz) == 0) == ((tid & j) == 0));
            v = takeMax ? (v > pv ? v : pv) : (v < pv ? v : pv);
        }
    }
    return v;
}

// ---------------------------------------------------------------------------
// Inline pivot: descending suffix scan over 4096 bins (4 per thread).
// ---------------------------------------------------------------------------
__device__ __forceinline__ int find_pivot(const unsigned* __restrict__ h, int k,
                                          int tid, unsigned* s_warp, int* s_piv) {
    int lane = tid & 31, wid = tid >> 5;
    unsigned cnt[4], tsum = 0;
    #pragma unroll
    for (int r = 0; r < 4; ++r) {
        cnt[r] = h[HB - 1 - (tid * 4 + r)];
        tsum += cnt[r];
    }
    unsigned inc = tsum;
    #pragma unroll
    for (int o = 1; o < 32; o <<= 1) {
        unsigned vv = __shfl_up_sync(0xffffffffu, inc, o);
        if (lane >= o) inc += vv;
    }
    if (lane == 31) s_warp[wid] = inc;
    __syncthreads();
    if (wid == 0) {
        unsigned w = s_warp[lane], wi = w;
        #pragma unroll
        for (int o = 1; o < 32; o <<= 1) {
            unsigned vv = __shfl_up_sync(0xffffffffu, wi, o);
            if (lane >= o) wi += vv;
        }
        s_warp[lane] = wi - w;
    }
    __syncthreads();
    unsigned P = s_warp[wid] + (inc - tsum);
    #pragma unroll
    for (int r = 0; r < 4; ++r) {
        P += cnt[r];
        if ((int)P >= k && (int)(P - cnt[r]) < k)
            *s_piv = HB - 1 - (tid * 4 + r);
    }
    __syncthreads();
    return *s_piv;
}

// ---------------------------------------------------------------------------
// K1 (fused front half): per-block histogram; last-arriving block of each
// task runs pivot -> selection rescan (L2 hits, smem compaction) ->
// sorts -> decode -> level sort -> emits sorted boxes/areas/keys/validmask.
// smem: [0:32K) cand (hist overlaps first 16K) | [32:40K) sbuf |
//       [40:48K) win | [48:64K) box | [64K:+1K) val
// ---------------------------------------------------------------------------
#define TK_SMEM (32768 + 8192 + 8192 + 16384 + 1024)

extern "C" __global__ void __launch_bounds__(1024)
topk_kernel(const float* __restrict__ obj,
            const float* __restrict__ deltas,
            const float* __restrict__ anchors) {
    int lvl, s0;
    slice_of(blockIdx.x, lvl, s0);
    int b = blockIdx.y;
    int n = c_lvl_n[lvl], base = c_lvl_base[lvl], k = c_lvl_k[lvl];
    int s1 = min(s0 + 3750, n);
    int task = b * 5 + lvl;
    const float* v = obj + (size_t)b * A_TOTAL + base;

    extern __shared__ unsigned char sm[];
    unsigned*           sh     = (unsigned*)sm;                      // 16KB (hist)
    unsigned long long* s_cand = (unsigned long long*)sm;            // 32KB
    unsigned long long* sbuf   = (unsigned long long*)(sm + 32768);  // 8KB
    unsigned long long* s_win  = (unsigned long long*)(sm + 40960);  // 8KB
    float4*             s_box  = (float4*)(sm + 49152);              // 16KB
    unsigned char*      s_val  = (unsigned char*)(sm + 65536);       // 1KB
    __shared__ unsigned s_warp[32];
    __shared__ int s_piv, s_last, s_nw, s_ncd;

    int tid = threadIdx.x, lane = tid & 31, wid = tid >> 5;

    // ---- histogram phase ----
    #pragma unroll
    for (int q = 0; q < HB / 1024; ++q) sh[q * 1024 + tid] = 0u;
    __syncthreads();
    {
        int i0 = s0 + tid, i1 = i0 + 1024, i2 = i0 + 2048, i3 = i0 + 3072;
        bool p0 = i0 < s1, p1 = i1 < s1, p2 = i2 < s1, p3 = i3 < s1;
        float f0 = p0 ? v[i0] : 0.f;
        float f1 = p1 ? v[i1] : 0.f;
        float f2 = p2 ? v[i2] : 0.f;
        float f3 = p3 ? v[i3] : 0.f;
        if (p0) atomicAdd(&sh[xf32(f0) >> HSHIFT], 1u);
        if (p1) atomicAdd(&sh[xf32(f1) >> HSHIFT], 1u);
        if (p2) atomicAdd(&sh[xf32(f2) >> HSHIFT], 1u);
        if (p3) atomicAdd(&sh[xf32(f3) >> HSHIFT], 1u);
    }
    __syncthreads();
    #pragma unroll
    for (int q = 0; q < HB / 1024; ++q) {
        unsigned c = sh[q * 1024 + tid];
        if (c) atomicAdd(&d_hist[task * HB + q * 1024 + tid], c);
    }

    // ---- task arrival; only the last block continues ----
    __threadfence();
    __syncthreads();
    if (tid == 0) {
        int r = atomicAdd(&d_taskbar[task], 1);
        s_last = (r == c_nblk[lvl] - 1) ? 1 : 0;
        if (s_last) d_taskbar[task] = 0;
    }
    __syncthreads();
    if (!s_last) return;
    __threadfence();

    // ---- pivot ----
    int pivot = find_pivot(d_hist + task * HB, k, tid, s_warp, &s_piv);

    // ---- selection rescan: compact winners / pivot-bin candidates to smem
    if (tid == 0) { s_nw = 0; s_ncd = 0; }
    __syncthreads();
    for (int i0 = tid; i0 < n; i0 += 4096) {
        int idx[4]; float f[4];
        #pragma unroll
        for (int r = 0; r < 4; ++r) {
            idx[r] = i0 + r * 1024;
            f[r] = (idx[r] < n) ? v[idx[r]] : 0.f;
        }
        #pragma unroll
        for (int r = 0; r < 4; ++r) {
            if (idx[r] >= n) continue;
            unsigned u = xf32(f[r]);
            int bin = (int)(u >> HSHIFT);
            if (bin < pivot) continue;
            unsigned long long key = ((unsigned long long)u << 32) |
                                     (unsigned long long)(0xFFFFFFFFu - (unsigned)idx[r]);
            if (bin > pivot) {
                s_win[atomicAdd(&s_nw, 1)] = key;
            } else {
                int pos = atomicAdd(&s_ncd, 1);
                if (pos < CCAP) s_cand[pos] = key;
            }
        }
    }
    __syncthreads();
    int direct = s_nw;
    int nc = min(s_ncd, CCAP);

    // ---- sort candidates; assemble winner list; sort to top_k order ----
    unsigned long long w;
    if (nc <= 1024) {
        unsigned long long cv = (tid < nc) ? s_cand[tid] : 0ULL;
        __syncthreads();
        cv = bsort1024(cv, sbuf, tid);
        s_cand[tid] = cv;
        __syncthreads();
    } else {
        int S = 2048; while (S < nc) S <<= 1;   // <= 4096
        for (int i = tid + nc; i < S; i += 1024) s_cand[i] = 0ULL;
        __syncthreads();
        for (unsigned sz = 2; sz <= (unsigned)S; sz <<= 1) {
            for (unsigned j = sz >> 1; j; j >>= 1) {
                for (int i = tid; i < S; i += 1024) {
                    unsigned l = (unsigned)i ^ j;
                    if (l > (unsigned)i && l < (unsigned)S) {
                        unsigned long long x = s_cand[i], y = s_cand[l];
                        bool up = ((i & sz) == 0);
                        if (up ? (x < y) : (x > y)) { s_cand[i] = y; s_cand[l] = x; }
                    }
                }
                __syncthreads();
            }
        }
    }
    w = 0ULL;
    if (tid < direct) w = s_win[tid];
    else if (tid < k) w = s_cand[tid - direct];
    __syncthreads();
    w = bsort1024(w, sbuf, tid);

    // ---- decode the tid-th ranked anchor ----
    unsigned long long key = 0ULL;
    if (tid < k) {
        int gi = base + (int)(0xFFFFFFFFu - (unsigned)(w & 0xFFFFFFFFULL));
        int p = lvl * 1000 + tid;
        int t = b * K_TOTAL + p;

        float logit = obj[(size_t)b * A_TOTAL + gi];
        float4 dl = *(const float4*)&deltas[((size_t)b * A_TOTAL + gi) * 4];
        float4 an = *(const float4*)&anchors[(size_t)gi * 4];

        float wa = __fsub_rn(an.z, an.x), ha = __fsub_rn(an.w, an.y);
        float cxa = __fadd_rn(an.x, __fmul_rn(0.5f, wa));
        float cya = __fadd_rn(an.y, __fmul_rn(0.5f, ha));

        const float CLIPV = 4.135166556742356f;
        float dw = fminf(dl.z, CLIPV);
        float dh = fminf(dl.w, CLIPV);

        float cx = __fadd_rn(__fmul_rn(dl.x, wa), cxa);
        float cy = __fadd_rn(__fmul_rn(dl.y, ha), cya);
        float ww = __fmul_rn(expf(dw), wa);
        float hh = __fmul_rn(expf(dh), ha);

        float x1 = __fsub_rn(cx, __fmul_rn(0.5f, ww));
        float y1 = __fsub_rn(cy, __fmul_rn(0.5f, hh));
        float x2 = __fadd_rn(cx, __fmul_rn(0.5f, ww));
        float y2 = __fadd_rn(cy, __fmul_rn(0.5f, hh));

        x1 = fminf(fmaxf(x1, 0.0f), 800.0f);
        y1 = fminf(fmaxf(y1, 0.0f), 800.0f);
        x2 = fminf(fmaxf(x2, 0.0f), 800.0f);
        y2 = fminf(fmaxf(y2, 0.0f), 800.0f);

        float score = __fdiv_rn(1.0f, __fadd_rn(1.0f, expf(-logit)));
        bool valid = (__fsub_rn(x2, x1) >= 0.001f) &&
                     (__fsub_rn(y2, y1) >= 0.001f) &&
                     (score >= 0.0f);
        float ssel = valid ? score : __int_as_float(0xff800000);

        d_boxes[(size_t)t * 4 + 0] = x1;
        d_boxes[(size_t)t * 4 + 1] = y1;
        d_boxes[(size_t)t * 4 + 2] = x2;
        d_boxes[(size_t)t * 4 + 3] = y2;
        d_score[t] = score;
        s_box[tid] = make_float4(x1, y1, x2, y2);
        s_val[tid] = valid ? 1 : 0;
        unsigned u = xf32(ssel);
        key = ((unsigned long long)u << 32) |
              (unsigned long long)(0xFFFFFFFFu - (unsigned)p);
    }
    __syncthreads();

    key = bsort1024(key, sbuf, tid);

    float4 ob = make_float4(0.f, 0.f, 0.f, 0.f);
    float ar = 0.f;
    unsigned char kp = 0;
    if (key != 0ULL) {
        int p = (int)(0xFFFFFFFFu - (unsigned)(key & 0xFFFFFFFFULL));
        int local = p - lvl * 1000;
        float4 bx = s_box[local];
        float off = (float)lvl * 1000.0f;
        ob.x = __fadd_rn(bx.x, off);
        ob.y = __fadd_rn(bx.y, off);
        ob.z = __fadd_rn(bx.z, off);
        ob.w = __fadd_rn(bx.w, off);
        ar = __fmul_rn(__fsub_rn(ob.z, ob.x), __fsub_rn(ob.w, ob.y));
        kp = s_val[local];
    }
    d_sbx[task * 1024 + tid] = ob;
    d_sar[task * 1024 + tid] = ar;
    d_skey[task * 1024 + tid] = key;
    unsigned bal = __ballot_sync(0xffffffffu, kp != 0);
    if (lane == 0) d_valmask[task * 32 + wid] = bal;

    // restore d_hist for next replay (last reader)
    #pragma unroll
    for (int q = 0; q < HB / 1024; ++q)
        d_hist[task * HB + q * 1024 + tid] = 0u;
}

// ---------------------------------------------------------------------------
// K2: suppression bit-matrix, triangular tiles (ic:32, jc:256), 256 threads.
// ---------------------------------------------------------------------------
extern "C" __global__ void __launch_bounds__(256)
supmask_kernel() {
    int e = blockIdx.x, task = blockIdx.y;
    int lvl = task % 5;
    int jc = c_tjc[e], ic = c_tic[e];
    if (lvl == 4 && (jc >= 2 || ic >= 16)) return;

    int tid = threadIdx.x;
    int lane = tid & 31;
    int Jg = jc * 8 + (tid >> 5);
    int j = jc * 256 + tid;
    int maxj = jc * 256 + (tid >> 5) * 32 + 31;

    __shared__ float4 s_bx[32];
    __shared__ float  s_ar[32];
    if (tid < 32) {
        s_bx[tid] = d_sbx[task * 1024 + ic * 32 + tid];
        s_ar[tid] = d_sar[task * 1024 + ic * 32 + tid];
    }
    __syncthreads();

    float4 bj = d_sbx[task * 1024 + j];
    float arj = d_sar[task * 1024 + j];

    #pragma unroll 4
    for (int ii = 0; ii < 32; ++ii) {
        int i = ic * 32 + ii;
        if (maxj <= i) continue;
        float4 bi = s_bx[ii];
        float ai = s_ar[ii];
        bool sup = false;
        if (j > i) {
            float xx1 = fmaxf(bi.x, bj.x);
            float yy1 = fmaxf(bi.y, bj.y);
            float xx2 = fminf(bi.z, bj.z);
            float yy2 = fminf(bi.w, bj.w);
            float w = fmaxf(__fsub_rn(xx2, xx1), 0.0f);
            float h = fmaxf(__fsub_rn(yy2, yy1), 0.0f);
            float inter = __fmul_rn(w, h);
            float uni = __fsub_rn(__fadd_rn(ai, arj), inter);
            float r = __fmaf_rn(-0.7f, uni, inter);
            float m = __fmul_rn(uni, 3.0e-7f);
            if (fabsf(r) > m) sup = (r > 0.0f);
            else if (uni > 0.0f) sup = (__fdiv_rn(inter, uni) > 0.7f);
        }
        unsigned bal = __ballot_sync(0xffffffffu, sup);
        if (lane == 0) d_sup[(task * 1024 + i) * 32 + Jg] = bal;
    }
}

// ---------------------------------------------------------------------------
// K3: greedy walk + per-level compaction; 5th-arriving block of each batch
// runs the cross-level merge.
// ---------------------------------------------------------------------------
extern "C" __global__ void __launch_bounds__(1024)
walkmerge_kernel(float* __restrict__ out) {
    int task = blockIdx.x;
    int b = task / 5;
    extern __shared__ unsigned char smraw[];
    unsigned* s_sup = (unsigned*)smraw;               // [1024][32]
    __shared__ unsigned s_aw[32];
    __shared__ int s_wsum[32], s_wbase[32];
    __shared__ int s_last;

    int tid = threadIdx.x, lane = tid & 31, wid = tid >> 5;

    for (int q = tid; q < 32768; q += 1024)
        s_sup[q] = d_sup[task * 32768 + q];
    __syncthreads();

    if (wid == 0) {
        unsigned alive = d_valmask[task * 32 + lane];
        #pragma unroll 1
        for (int c = 0; c < 32; ++c) {
            unsigned a = __shfl_sync(0xffffffffu, alive, c);
            if (a) {
                unsigned w[32];
                #pragma unroll
                for (int t = 0; t < 32; ++t)
                    w[t] = s_sup[(c * 32 + t) * 32 + c];
                #pragma unroll
                for (int t = 0; t < 32; ++t) {
                    unsigned m = (unsigned)(-(int)((a >> t) & 1u));
                    a &= ~(w[t] & m);
                }
                #pragma unroll
                for (int t = 0; t < 32; ++t) {
                    unsigned r = s_sup[(c * 32 + t) * 32 + lane];
                    unsigned m = (unsigned)(-(int)((a >> t) & 1u));
                    alive &= ~(r & m);
                }
            }
            if (lane == c) alive = a;
        }
        s_aw[lane] = alive;
    }
    __syncthreads();

    bool keep = (s_aw[wid] >> lane) & 1u;
    unsigned bal = __ballot_sync(0xffffffffu, keep);
    if (lane == 0) s_wsum[wid] = __popc(bal);
    __syncthreads();
    if (tid == 0) {
        int s = 0;
        for (int w2 = 0; w2 < 32; ++w2) { s_wbase[w2] = s; s += s_wsum[w2]; }
        d_lvl_cnt[task] = s;
    }
    __syncthreads();
    if (keep) {
        int slot = s_wbase[wid] + __popc(bal & ((1u << lane) - 1u));
        d_lvl_keys[task * 1024 + slot] = d_skey[task * 1024 + tid];
    }

    __syncthreads();
    __threadfence();
    if (tid == 0) {
        int r = atomicAdd(&d_bar[b], 1);
        s_last = (r == 4) ? 1 : 0;
        if (r == 4) d_bar[b] = 0;
    }
    __syncthreads();
    if (!s_last) return;
    __threadfence();

    unsigned long long (*s_keys)[1024] = (unsigned long long (*)[1024])smraw;
    __shared__ int s_cnt[5];
    if (tid < 5) s_cnt[tid] = d_lvl_cnt[b * 5 + tid];
    __syncthreads();

    for (int i = tid; i < 5 * 1024; i += 1024) {
        int lvl = i >> 10, r = i & 1023;
        if (r < s_cnt[lvl])
            s_keys[lvl][r] = d_lvl_keys[(b * 5 + lvl) * 1024 + r];
    }
    __syncthreads();

    int total = s_cnt[0] + s_cnt[1] + s_cnt[2] + s_cnt[3] + s_cnt[4];

    for (int i = tid; i < 5 * 1024; i += 1024) {
        int lvl = i >> 10, r = i & 1023;
        if (r >= s_cnt[lvl]) continue;
        unsigned long long key = s_keys[lvl][r];
        int rank = r;
        #pragma unroll
        for (int o = 0; o < 5; ++o) {
            if (o == lvl) continue;
            int lo = 0, hi = s_cnt[o];
            while (lo < hi) {
                int mid = (lo + hi) >> 1;
                if (s_keys[o][mid] > key) lo = mid + 1; else hi = mid;
            }
            rank += lo;
        }
        if (rank < POST_NMS) {
            int p = (int)(0xFFFFFFFFu - (unsigned)(key & 0xFFFFFFFFULL));
            float4 bx = *(const float4*)&d_boxes[((size_t)b * K_TOTAL + p) * 4];
            float* o2 = out + ((size_t)b * POST_NMS + rank) * 5;
            o2[0] = bx.x; o2[1] = bx.y; o2[2] = bx.z; o2[3] = bx.w;
            o2[4] = d_score[b * K_TOTAL + p];
        }
    }
    if (tid < POST_NMS && tid >= total) {
        float* o2 = out + ((size_t)b * POST_NMS + tid) * 5;
        o2[0] = 0.f; o2[1] = 0.f; o2[2] = 0.f; o2[3] = 0.f; o2[4] = 0.f;
    }
}

// ---------------------------------------------------------------------------
extern "C" void kernel_launch(void* const* d_in, const int* in_sizes, int n_in,
                              void* d_out, int out_size) {
    const float* obj     = (const float*)d_in[0];
    const float* deltas  = (const float*)d_in[1];
    const float* anchors = (const float*)d_in[2];
    float* out = (float*)d_out;

    cudaFuncSetAttribute(topk_kernel,
                         cudaFuncAttributeMaxDynamicSharedMemorySize, TK_SMEM);
    cudaFuncSetAttribute(walkmerge_kernel,
                         cudaFuncAttributeMaxDynamicSharedMemorySize, 131072);

    topk_kernel<<<dim3(NSLICE, NB), 1024, TK_SMEM>>>(obj, deltas, anchors);
    supmask_kernel<<<dim3(80, NTASK), 256>>>();
    walkmerge_kernel<<<NTASK, 1024, 131072>>>(out);
}

// round 9
// speedup vs baseline: 1.0752x; 1.0752x over previous
#include <cuda_runtime.h>
#include <cstdint>

#define NB 4
#define A_TOTAL 159882
#define K_TOTAL 4507
#define POST_NMS 1000
#define NTASK (NB * 5)
#define HB 4096             // 12-bit histogram bins
#define HSHIFT 20
#define CCAP 4096
#define NSLICE 44           // work-balanced slices per batch image

__constant__ int c_lvl_n[5]    = {120000, 30000, 7500, 1875, 507};
__constant__ int c_lvl_base[5] = {0, 120000, 150000, 157500, 159375};
__constant__ int c_lvl_k[5]    = {1000, 1000, 1000, 1000, 507};
__constant__ int c_nblk[5]     = {32, 8, 2, 1, 1};

// supmask triangular tiles: (jc: j-block of 256, ic: i-block of 32),
// tile present iff ic <= 8*jc+7 -> 80 tiles
__constant__ unsigned char c_tjc[80] = {
    0,0,0,0,0,0,0,0,
    1,1,1,1,1,1,1,1,1,1,1,1,1,1,1,1,
    2,2,2,2,2,2,2,2,2,2,2,2,2,2,2,2,2,2,2,2,2,2,2,2,
    3,3,3,3,3,3,3,3,3,3,3,3,3,3,3,3,3,3,3,3,3,3,3,3,3,3,3,3,3,3,3,3};
__constant__ unsigned char c_tic[80] = {
    0,1,2,3,4,5,6,7,
    0,1,2,3,4,5,6,7,8,9,10,11,12,13,14,15,
    0,1,2,3,4,5,6,7,8,9,10,11,12,13,14,15,16,17,18,19,20,21,22,23,
    0,1,2,3,4,5,6,7,8,9,10,11,12,13,14,15,16,17,18,19,20,21,22,23,
    24,25,26,27,28,29,30,31};

// static scratch (zero-initialized at load; every kernel that dirties a
// buffer restores it before exit -> graph-replay invariant)
__device__ unsigned           d_hist[NTASK * HB];
__device__ int                d_cnt[2 * NTASK];      // [t]=win(=direct), [20+t]=cand
__device__ int                d_taskbar[NTASK];
__device__ int                d_bar[NB];
__device__ unsigned long long d_win[NTASK * 1024];
__device__ unsigned long long d_cand[NTASK * CCAP];
__device__ float              d_boxes[NB * K_TOTAL * 4];
__device__ float              d_score[NB * K_TOTAL];
__device__ float4             d_sbx[NTASK * 1024];
__device__ float              d_sar[NTASK * 1024];
__device__ unsigned long long d_skey[NTASK * 1024];
__device__ unsigned           d_valmask[NTASK * 32];
__device__ unsigned           d_sup[NTASK * 1024 * 32];
__device__ unsigned long long d_lvl_keys[NTASK * 1024];
__device__ int                d_lvl_cnt[NTASK];

__device__ __forceinline__ unsigned xf32(float f) {
    unsigned u = __float_as_uint(f);
    return (u & 0x80000000u) ? ~u : (u | 0x80000000u);
}

// slice table: index -> (lvl, s0). counts {32,8,2,1,1}, chunk 3750.
__device__ __forceinline__ void slice_of(int s, int& lvl, int& s0) {
    if (s < 32)      { lvl = 0; s0 = s * 3750; }
    else if (s < 40) { lvl = 1; s0 = (s - 32) * 3750; }
    else if (s < 42) { lvl = 2; s0 = (s - 40) * 3750; }
    else if (s == 42){ lvl = 3; s0 = 0; }
    else             { lvl = 4; s0 = 0; }
}

// ---------------------------------------------------------------------------
// Hybrid bitonic sort: 1024 u64 keys descending, one per thread.
// ---------------------------------------------------------------------------
__device__ __forceinline__ unsigned long long
bsort1024(unsigned long long v, unsigned long long* sbuf, int tid) {
    #pragma unroll
    for (unsigned sz = 2; sz <= 32; sz <<= 1) {
        #pragma unroll
        for (unsigned j = sz >> 1; j; j >>= 1) {
            unsigned long long pv = __shfl_xor_sync(0xffffffffu, v, j);
            bool takeMax = (((tid & sz) == 0) == ((tid & j) == 0));
            v = takeMax ? (v > pv ? v : pv) : (v < pv ? v : pv);
        }
    }
    #pragma unroll
    for (unsigned sz = 64; sz <= 1024; sz <<= 1) {
        #pragma unroll 1
        for (unsigned j = sz >> 1; j >= 32; j >>= 1) {
            sbuf[tid] = v;
            __syncthreads();
            unsigned long long pv = sbuf[tid ^ j];
            bool takeMax = (((tid & sz) == 0) == ((tid & j) == 0));
            v = takeMax ? (v > pv ? v : pv) : (v < pv ? v : pv);
            __syncthreads();
        }
        #pragma unroll
        for (unsigned j = 16; j; j >>= 1) {
            unsigned long long pv = __shfl_xor_sync(0xffffffffu, v, j);
            bool takeMax = (((tid & sz) == 0) == ((tid & j) == 0));
            v = takeMax ? (v > pv ? v : pv) : (v < pv ? v : pv);
        }
    }
    return v;
}

// ---------------------------------------------------------------------------
// K1: smem-aggregated 12-bit histogram. grid (44 balanced slices, NB).
// ---------------------------------------------------------------------------
extern "C" __global__ void __launch_bounds__(1024)
hist_kernel(const float* __restrict__ obj) {
    int lvl, s0;
    slice_of(blockIdx.x, lvl, s0);
    int bb = blockIdx.y;
    int n = c_lvl_n[lvl];
    int s1 = min(s0 + 3750, n);
    int task = bb * 5 + lvl;
    const float* v = obj + (size_t)bb * A_TOTAL + c_lvl_base[lvl];

    __shared__ unsigned sh[HB];
    int tid = threadIdx.x;
    #pragma unroll
    for (int q = 0; q < HB / 1024; ++q) sh[q * 1024 + tid] = 0u;
    __syncthreads();

    int i0 = s0 + tid, i1 = i0 + 1024, i2 = i0 + 2048, i3 = i0 + 3072;
    bool p0 = i0 < s1, p1 = i1 < s1, p2 = i2 < s1, p3 = i3 < s1;
    float f0 = p0 ? v[i0] : 0.f;
    float f1 = p1 ? v[i1] : 0.f;
    float f2 = p2 ? v[i2] : 0.f;
    float f3 = p3 ? v[i3] : 0.f;
    if (p0) atomicAdd(&sh[xf32(f0) >> HSHIFT], 1u);
    if (p1) atomicAdd(&sh[xf32(f1) >> HSHIFT], 1u);
    if (p2) atomicAdd(&sh[xf32(f2) >> HSHIFT], 1u);
    if (p3) atomicAdd(&sh[xf32(f3) >> HSHIFT], 1u);
    __syncthreads();

    #pragma unroll
    for (int q = 0; q < HB / 1024; ++q) {
        unsigned c = sh[q * 1024 + tid];
        if (c) atomicAdd(&d_hist[task * HB + q * 1024 + tid], c);
    }
}

// ---------------------------------------------------------------------------
// Inline pivot: descending suffix scan over 4096 bins (4 per thread).
// ---------------------------------------------------------------------------
__device__ __forceinline__ int find_pivot(const unsigned* __restrict__ h, int k,
                                          int tid, unsigned* s_warp, int* s_piv) {
    int lane = tid & 31, wid = tid >> 5;
    unsigned cnt[4], tsum = 0;
    #pragma unroll
    for (int r = 0; r < 4; ++r) {
        cnt[r] = h[HB - 1 - (tid * 4 + r)];
        tsum += cnt[r];
    }
    unsigned inc = tsum;
    #pragma unroll
    for (int o = 1; o < 32; o <<= 1) {
        unsigned vv = __shfl_up_sync(0xffffffffu, inc, o);
        if (lane >= o) inc += vv;
    }
    if (lane == 31) s_warp[wid] = inc;
    __syncthreads();
    if (wid == 0) {
        unsigned w = s_warp[lane], wi = w;
        #pragma unroll
        for (int o = 1; o < 32; o <<= 1) {
            unsigned vv = __shfl_up_sync(0xffffffffu, wi, o);
            if (lane >= o) wi += vv;
        }
        s_warp[lane] = wi - w;
    }
    __syncthreads();
    unsigned P = s_warp[wid] + (inc - tsum);
    #pragma unroll
    for (int r = 0; r < 4; ++r) {
        P += cnt[r];
        if ((int)P >= k && (int)(P - cnt[r]) < k)
            *s_piv = HB - 1 - (tid * 4 + r);
    }
    __syncthreads();
    return *s_piv;
}

// ---------------------------------------------------------------------------
// K2: selection scan (wide, balanced slices) + per-task LAST-BLOCK tail that
// runs sorts + decode + level sort, then restores d_hist/d_cnt.
// smem: [0:32K) cand | [32:40K) sbuf | [40:56K) box | [56K:+1K) val
// ---------------------------------------------------------------------------
#define SD_SMEM (32768 + 8192 + 16384 + 1024)

extern "C" __global__ void __launch_bounds__(1024)
selectdecode_kernel(const float* __restrict__ obj,
                    const float* __restrict__ deltas,
                    const float* __restrict__ anchors) {
    int lvl, s0;
    slice_of(blockIdx.x, lvl, s0);
    int b = blockIdx.y;
    int n = c_lvl_n[lvl], base = c_lvl_base[lvl], k = c_lvl_k[lvl];
    int s1 = min(s0 + 3750, n);
    int task = b * 5 + lvl;
    const float* v = obj + (size_t)b * A_TOTAL + base;

    extern __shared__ unsigned char sm[];
    unsigned long long* s_cand = (unsigned long long*)sm;            // 4096
    unsigned long long* sbuf   = (unsigned long long*)(sm + 32768);  // 1024
    float4*             s_box  = (float4*)(sm + 40960);              // 1024
    unsigned char*      s_val  = (unsigned char*)(sm + 57344);       // 1024
    __shared__ unsigned s_warp[32];
    __shared__ int s_piv, s_last;

    int tid = threadIdx.x, lane = tid & 31, wid = tid >> 5;

    // ---- selection phase (this block's slice) ----
    {
        int idx[4];
        float f[4];
        #pragma unroll
        for (int r = 0; r < 4; ++r) {
            idx[r] = s0 + tid + r * 1024;
            f[r] = (idx[r] < s1) ? v[idx[r]] : 0.f;
        }
        int pivot = find_pivot(d_hist + task * HB, k, tid, s_warp, &s_piv);
        #pragma unroll
        for (int r = 0; r < 4; ++r) {
            if (idx[r] >= s1) continue;
            unsigned u = xf32(f[r]);
            int bin = (int)(u >> HSHIFT);
            if (bin < pivot) continue;
            unsigned long long key = ((unsigned long long)u << 32) |
                                     (unsigned long long)(0xFFFFFFFFu - (unsigned)idx[r]);
            if (bin > pivot) {
                int pos = atomicAdd(&d_cnt[task], 1);
                d_win[task * 1024 + pos] = key;
            } else {
                int pos = atomicAdd(&d_cnt[NTASK + task], 1);
                if (pos < CCAP) d_cand[task * CCAP + pos] = key;
            }
        }
    }

    // ---- arrival; only the task's last block continues into the tail ----
    __threadfence();
    __syncthreads();
    if (tid == 0) {
        int r = atomicAdd(&d_taskbar[task], 1);
        s_last = (r == c_nblk[lvl] - 1) ? 1 : 0;
        if (s_last) d_taskbar[task] = 0;
    }
    __syncthreads();
    if (!s_last) return;
    __threadfence();

    int direct = d_cnt[task];
    int nc = min(d_cnt[NTASK + task], CCAP);

    // ---- sort candidates; assemble winners; sort to top_k order ----
    unsigned long long w;
    if (nc <= 1024) {
        unsigned long long cv = (tid < nc) ? d_cand[task * CCAP + tid] : 0ULL;
        cv = bsort1024(cv, sbuf, tid);
        sbuf[tid] = cv;
        __syncthreads();
        w = 0ULL;
        if (tid < direct) w = d_win[task * 1024 + tid];
        else if (tid < k) w = sbuf[tid - direct];
        __syncthreads();
    } else {
        int S = 2048; while (S < nc) S <<= 1;   // <= 4096
        for (int i = tid; i < S; i += 1024)
            s_cand[i] = (i < nc) ? d_cand[task * CCAP + i] : 0ULL;
        __syncthreads();
        for (unsigned sz = 2; sz <= (unsigned)S; sz <<= 1) {
            for (unsigned j = sz >> 1; j; j >>= 1) {
                for (int i = tid; i < S; i += 1024) {
                    unsigned l = (unsigned)i ^ j;
                    if (l > (unsigned)i && l < (unsigned)S) {
                        unsigned long long x = s_cand[i], y = s_cand[l];
                        bool up = ((i & sz) == 0);
                        if (up ? (x < y) : (x > y)) { s_cand[i] = y; s_cand[l] = x; }
                    }
                }
                __syncthreads();
            }
        }
        w = 0ULL;
        if (tid < direct) w = d_win[task * 1024 + tid];
        else if (tid < k) w = s_cand[tid - direct];
        __syncthreads();
    }
    w = bsort1024(w, sbuf, tid);

    // ---- decode the tid-th ranked anchor ----
    unsigned long long key = 0ULL;
    if (tid < k) {
        int gi = base + (int)(0xFFFFFFFFu - (unsigned)(w & 0xFFFFFFFFULL));
        int p = lvl * 1000 + tid;
        int t = b * K_TOTAL + p;

        float logit = obj[(size_t)b * A_TOTAL + gi];
        float4 dl = *(const float4*)&deltas[((size_t)b * A_TOTAL + gi) * 4];
        float4 an = *(const float4*)&anchors[(size_t)gi * 4];

        float wa = __fsub_rn(an.z, an.x), ha = __fsub_rn(an.w, an.y);
        float cxa = __fadd_rn(an.x, __fmul_rn(0.5f, wa));
        float cya = __fadd_rn(an.y, __fmul_rn(0.5f, ha));

        const float CLIPV = 4.135166556742356f;
        float dw = fminf(dl.z, CLIPV);
        float dh = fminf(dl.w, CLIPV);

        float cx = __fadd_rn(__fmul_rn(dl.x, wa), cxa);
        float cy = __fadd_rn(__fmul_rn(dl.y, ha), cya);
        float ww = __fmul_rn(expf(dw), wa);
        float hh = __fmul_rn(expf(dh), ha);

        float x1 = __fsub_rn(cx, __fmul_rn(0.5f, ww));
        float y1 = __fsub_rn(cy, __fmul_rn(0.5f, hh));
        float x2 = __fadd_rn(cx, __fmul_rn(0.5f, ww));
        float y2 = __fadd_rn(cy, __fmul_rn(0.5f, hh));

        x1 = fminf(fmaxf(x1, 0.0f), 800.0f);
        y1 = fminf(fmaxf(y1, 0.0f), 800.0f);
        x2 = fminf(fmaxf(x2, 0.0f), 800.0f);
        y2 = fminf(fmaxf(y2, 0.0f), 800.0f);

        float score = __fdiv_rn(1.0f, __fadd_rn(1.0f, expf(-logit)));
        bool valid = (__fsub_rn(x2, x1) >= 0.001f) &&
                     (__fsub_rn(y2, y1) >= 0.001f) &&
                     (score >= 0.0f);
        float ssel = valid ? score : __int_as_float(0xff800000);

        d_boxes[(size_t)t * 4 + 0] = x1;
        d_boxes[(size_t)t * 4 + 1] = y1;
        d_boxes[(size_t)t * 4 + 2] = x2;
        d_boxes[(size_t)t * 4 + 3] = y2;
        d_score[t] = score;
        s_box[tid] = make_float4(x1, y1, x2, y2);
        s_val[tid] = valid ? 1 : 0;
        unsigned u = xf32(ssel);
        key = ((unsigned long long)u << 32) |
              (unsigned long long)(0xFFFFFFFFu - (unsigned)p);
    }
    __syncthreads();

    key = bsort1024(key, sbuf, tid);

    float4 ob = make_float4(0.f, 0.f, 0.f, 0.f);
    float ar = 0.f;
    unsigned char kp = 0;
    if (key != 0ULL) {
        int p = (int)(0xFFFFFFFFu - (unsigned)(key & 0xFFFFFFFFULL));
        int local = p - lvl * 1000;
        float4 bx = s_box[local];
        float off = (float)lvl * 1000.0f;
        ob.x = __fadd_rn(bx.x, off);
        ob.y = __fadd_rn(bx.y, off);
        ob.z = __fadd_rn(bx.z, off);
        ob.w = __fadd_rn(bx.w, off);
        ar = __fmul_rn(__fsub_rn(ob.z, ob.x), __fsub_rn(ob.w, ob.y));
        kp = s_val[local];
    }
    d_sbx[task * 1024 + tid] = ob;
    d_sar[task * 1024 + tid] = ar;
    d_skey[task * 1024 + tid] = key;
    unsigned bal = __ballot_sync(0xffffffffu, kp != 0);
    if (lane == 0) d_valmask[task * 32 + wid] = bal;

    // restore scratch for next replay (last reader of both)
    #pragma unroll
    for (int q = 0; q < HB / 1024; ++q)
        d_hist[task * HB + q * 1024 + tid] = 0u;
    if (tid == 0) { d_cnt[task] = 0; d_cnt[NTASK + task] = 0; }
}

// ---------------------------------------------------------------------------
// K3: suppression bit-matrix, triangular tiles (ic:32, jc:256), 256 threads.
// ---------------------------------------------------------------------------
extern "C" __global__ void __launch_bounds__(256)
supmask_kernel() {
    int e = blockIdx.x, task = blockIdx.y;
    int lvl = task % 5;
    int jc = c_tjc[e], ic = c_tic[e];
    if (lvl == 4 && (jc >= 2 || ic >= 16)) return;

    int tid = threadIdx.x;
    int lane = tid & 31;
    int Jg = jc * 8 + (tid >> 5);
    int j = jc * 256 + tid;
    int maxj = jc * 256 + (tid >> 5) * 32 + 31;

    __shared__ float4 s_bx[32];
    __shared__ float  s_ar[32];
    if (tid < 32) {
        s_bx[tid] = d_sbx[task * 1024 + ic * 32 + tid];
        s_ar[tid] = d_sar[task * 1024 + ic * 32 + tid];
    }
    __syncthreads();

    float4 bj = d_sbx[task * 1024 + j];
    float arj = d_sar[task * 1024 + j];

    #pragma unroll 4
    for (int ii = 0; ii < 32; ++ii) {
        int i = ic * 32 + ii;
        if (maxj <= i) continue;
        float4 bi = s_bx[ii];
        float ai = s_ar[ii];
        bool sup = false;
        if (j > i) {
            float xx1 = fmaxf(bi.x, bj.x);
            float yy1 = fmaxf(bi.y, bj.y);
            float xx2 = fminf(bi.z, bj.z);
            float yy2 = fminf(bi.w, bj.w);
            float w = fmaxf(__fsub_rn(xx2, xx1), 0.0f);
            float h = fmaxf(__fsub_rn(yy2, yy1), 0.0f);
            float inter = __fmul_rn(w, h);
            float uni = __fsub_rn(__fadd_rn(ai, arj), inter);
            float r = __fmaf_rn(-0.7f, uni, inter);
            float m = __fmul_rn(uni, 3.0e-7f);
            if (fabsf(r) > m) sup = (r > 0.0f);
            else if (uni > 0.0f) sup = (__fdiv_rn(inter, uni) > 0.7f);
        }
        unsigned bal = __ballot_sync(0xffffffffu, sup);
        if (lane == 0) d_sup[(task * 1024 + i) * 32 + Jg] = bal;
    }
}

// ---------------------------------------------------------------------------
// K4: greedy walk + per-level compaction; 5th-arriving block of each batch
// runs the cross-level merge.
// ---------------------------------------------------------------------------
extern "C" __global__ void __launch_bounds__(1024)
walkmerge_kernel(float* __restrict__ out) {
    int task = blockIdx.x;
    int b = task / 5;
    extern __shared__ unsigned char smraw[];
    unsigned* s_sup = (unsigned*)smraw;               // [1024][32]
    __shared__ unsigned s_aw[32];
    __shared__ int s_wsum[32], s_wbase[32];
    __shared__ int s_last;

    int tid = threadIdx.x, lane = tid & 31, wid = tid >> 5;

    for (int q = tid; q < 32768; q += 1024)
        s_sup[q] = d_sup[task * 32768 + q];
    __syncthreads();

    if (wid == 0) {
        unsigned alive = d_valmask[task * 32 + lane];
        #pragma unroll 1
        for (int c = 0; c < 32; ++c) {
            unsigned a = __shfl_sync(0xffffffffu, alive, c);
            if (a) {
                unsigned w[32];
                #pragma unroll
                for (int t = 0; t < 32; ++t)
                    w[t] = s_sup[(c * 32 + t) * 32 + c];
                #pragma unroll
                for (int t = 0; t < 32; ++t) {
                    unsigned m = (unsigned)(-(int)((a >> t) & 1u));
                    a &= ~(w[t] & m);
                }
                #pragma unroll
                for (int t = 0; t < 32; ++t) {
                    unsigned r = s_sup[(c * 32 + t) * 32 + lane];
                    unsigned m = (unsigned)(-(int)((a >> t) & 1u));
                    alive &= ~(r & m);
                }
            }
            if (lane == c) alive = a;
        }
        s_aw[lane] = alive;
    }
    __syncthreads();

    bool keep = (s_aw[wid] >> lane) & 1u;
    unsigned bal = __ballot_sync(0xffffffffu, keep);
    if (lane == 0) s_wsum[wid] = __popc(bal);
    __syncthreads();
    if (tid == 0) {
        int s = 0;
        for (int w2 = 0; w2 < 32; ++w2) { s_wbase[w2] = s; s += s_wsum[w2]; }
        d_lvl_cnt[task] = s;
    }
    __syncthreads();
    if (keep) {
        int slot = s_wbase[wid] + __popc(bal & ((1u << lane) - 1u));
        d_lvl_keys[task * 1024 + slot] = d_skey[task * 1024 + tid];
    }

    __syncthreads();
    __threadfence();
    if (tid == 0) {
        int r = atomicAdd(&d_bar[b], 1);
        s_last = (r == 4) ? 1 : 0;
        if (r == 4) d_bar[b] = 0;
    }
    __syncthreads();
    if (!s_last) return;
    __threadfence();

    unsigned long long (*s_keys)[1024] = (unsigned long long (*)[1024])smraw;
    __shared__ int s_cnt[5];
    if (tid < 5) s_cnt[tid] = d_lvl_cnt[b * 5 + tid];
    __syncthreads();

    for (int i = tid; i < 5 * 1024; i += 1024) {
        int lvl = i >> 10, r = i & 1023;
        if (r < s_cnt[lvl])
            s_keys[lvl][r] = d_lvl_keys[(b * 5 + lvl) * 1024 + r];
    }
    __syncthreads();

    int total = s_cnt[0] + s_cnt[1] + s_cnt[2] + s_cnt[3] + s_cnt[4];

    for (int i = tid; i < 5 * 1024; i += 1024) {
        int lvl = i >> 10, r = i & 1023;
        if (r >= s_cnt[lvl]) continue;
        unsigned long long key = s_keys[lvl][r];
        int rank = r;
        #pragma unroll
        for (int o = 0; o < 5; ++o) {
            if (o == lvl) continue;
            int lo = 0, hi = s_cnt[o];
            while (lo < hi) {
                int mid = (lo + hi) >> 1;
                if (s_keys[o][mid] > key) lo = mid + 1; else hi = mid;
            }
            rank += lo;
        }
        if (rank < POST_NMS) {
            int p = (int)(0xFFFFFFFFu - (unsigned)(key & 0xFFFFFFFFULL));
            float4 bx = *(const float4*)&d_boxes[((size_t)b * K_TOTAL + p) * 4];
            float* o2 = out + ((size_t)b * POST_NMS + rank) * 5;
            o2[0] = bx.x; o2[1] = bx.y; o2[2] = bx.z; o2[3] = bx.w;
            o2[4] = d_score[b * K_TOTAL + p];
        }
    }
    if (tid < POST_NMS && tid >= total) {
        float* o2 = out + ((size_t)b * POST_NMS + tid) * 5;
        o2[0] = 0.f; o2[1] = 0.f; o2[2] = 0.f; o2[3] = 0.f; o2[4] = 0.f;
    }
}

// ---------------------------------------------------------------------------
extern "C" void kernel_launch(void* const* d_in, const int* in_sizes, int n_in,
                              void* d_out, int out_size) {
    const float* obj     = (const float*)d_in[0];
    const float* deltas  = (const float*)d_in[1];
    const float* anchors = (const float*)d_in[2];
    float* out = (float*)d_out;

    cudaFuncSetAttribute(selectdecode_kernel,
                         cudaFuncAttributeMaxDynamicSharedMemorySize, SD_SMEM);
    cudaFuncSetAttribute(walkmerge_kernel,
                         cudaFuncAttributeMaxDynamicSharedMemorySize, 131072);

    hist_kernel<<<dim3(NSLICE, NB), 1024>>>(obj);
    selectdecode_kernel<<<dim3(NSLICE, NB), 1024, SD_SMEM>>>(obj, deltas, anchors);
    supmask_kernel<<<dim3(80, NTASK), 256>>>();
    walkmerge_kernel<<<NTASK, 1024, 131072>>>(out);
}